// round 8
// baseline (speedup 1.0000x reference)
#include <cuda_runtime.h>
#include <cuda_bf16.h>
#include <cstdint>

// ---------------- problem shape (fixed) ----------------
constexpr int BN = 8, LN = 1024, SN = 1024, HN = 16, EN = 64, DN = 64;

constexpr int MQ  = 64;            // queries per CTA
constexpr int NK  = 64;            // keys per chunk
constexpr int NCH = SN / NK;       // 16
constexpr int NTHREADS = 256;      // 8 warps
constexpr int CAPQ = 32;           // candidate capacity per (row, quarter)

// ---------------- smem layout (bytes) ----------------
constexpr int QTILE   = MQ * 144;                  // 9216 (hi or lo)
constexpr int OFF_QHI = 0;
constexpr int OFF_QLO = QTILE;                     // 9216
constexpr int KTILE   = NK * 144;                  // 9216
constexpr int KBUF    = 2 * KTILE;                 // hi+lo = 18432
constexpr int OFF_KB  = 2 * QTILE;                 // 18432 ; 2 buffers
constexpr int OFF_CV  = OFF_KB + 2 * KBUF;         // 55296 ; float[64*4*CAPQ]
constexpr int OFF_CI  = OFF_CV + MQ * 4 * CAPQ * 4;// 88064 ; u16
constexpr int OFF_CNT = OFF_CI + MQ * 4 * CAPQ * 2;// 104448 ; int[256]
constexpr int OFF_CSUM= OFF_CNT + MQ * 4 * 4;      // 105472 ; float[256]
constexpr int OFF_THR = OFF_CSUM + MQ * 4 * 4;     // 106496 ; uint[64]
constexpr int SMEM_BYTES = OFF_THR + MQ * 4;       // 106752  (2 CTAs/SM)

// ---------------- prepped bf16 hi/lo tensors ([b][h][l|s][e]) ----------------
__device__ __nv_bfloat16 g_qhi[(size_t)BN*HN*LN*EN];
__device__ __nv_bfloat16 g_qlo[(size_t)BN*HN*LN*EN];
__device__ __nv_bfloat16 g_khi[(size_t)BN*HN*SN*EN];
__device__ __nv_bfloat16 g_klo[(size_t)BN*HN*SN*EN];

// ---------------- helpers ----------------
__device__ __forceinline__ uint32_t smem_to_u32(const void* p) {
    uint32_t a;
    asm("{ .reg .u64 t; cvta.to.shared.u64 t, %1; cvt.u32.u64 %0, t; }" : "=r"(a) : "l"(p));
    return a;
}
__device__ __forceinline__ void ldsm_x4(uint32_t r[4], uint32_t addr) {
    asm volatile("ldmatrix.sync.aligned.m8n8.x4.shared.b16 {%0,%1,%2,%3}, [%4];"
                 : "=r"(r[0]), "=r"(r[1]), "=r"(r[2]), "=r"(r[3]) : "r"(addr));
}
__device__ __forceinline__ void mma_bf16(float d[4], const uint32_t a[4],
                                         uint32_t b0, uint32_t b1) {
    asm volatile("mma.sync.aligned.m16n8k16.row.col.f32.bf16.bf16.f32 "
                 "{%0,%1,%2,%3}, {%4,%5,%6,%7}, {%8,%9}, {%0,%1,%2,%3};"
                 : "+f"(d[0]), "+f"(d[1]), "+f"(d[2]), "+f"(d[3])
                 : "r"(a[0]), "r"(a[1]), "r"(a[2]), "r"(a[3]), "r"(b0), "r"(b1));
}
// monotone float<->uint encoding for atomicMax on floats (any sign)
__device__ __forceinline__ uint32_t fenc(float x) {
    uint32_t u = __float_as_uint(x);
    return (u & 0x80000000u) ? ~u : (u | 0x80000000u);
}
__device__ __forceinline__ float fdec(uint32_t e) {
    uint32_t u = (e & 0x80000000u) ? (e & 0x7fffffffu) | 0x80000000u : ~e;
    // note: enc(x)=u|0x8000.. for x>=0 -> dec: clear top bit? handle both branches:
    return __uint_as_float((e & 0x80000000u) ? (e & 0x7fffffffu) : ~e);
}

// ---------------- prep: fp32 -> bf16 hi/lo, [b,l,h,e] -> [b,h,l,e] ----------------
__global__ void prep_kernel(const float* __restrict__ Q, const float* __restrict__ K) {
    const size_t total = (size_t)BN * LN * HN * EN;
    for (size_t i = (size_t)blockIdx.x * blockDim.x + threadIdx.x; i < total;
         i += (size_t)gridDim.x * blockDim.x) {
        const int e = (int)(i & 63);
        const int h = (int)((i >> 6) & 15);
        const int l = (int)((i >> 10) & 1023);
        const int b = (int)(i >> 20);
        const size_t o = ((((size_t)b * HN + h) * LN + l) << 6) + e;

        float q = Q[i] * 0.125f;
        __nv_bfloat16 qh = __float2bfloat16(q);
        g_qhi[o] = qh;
        g_qlo[o] = __float2bfloat16(q - __bfloat162float(qh));

        float k = K[i];
        __nv_bfloat16 kh = __float2bfloat16(k);
        g_khi[o] = kh;
        g_klo[o] = __float2bfloat16(k - __bfloat162float(kh));
    }
}

// ---------------- main kernel ----------------
__global__ __launch_bounds__(NTHREADS, 2)
void sparsemax_attn_mma(const float* __restrict__ V, float* __restrict__ O) {
    extern __shared__ char smem[];
    const uint32_t sb = smem_to_u32(smem);
    const int tid = threadIdx.x, lane = tid & 31, warp = tid >> 5;
    const int wq = warp & 1, wk = warp >> 1;        // 2 q-groups x 4 k-groups
    const int l0 = blockIdx.x * MQ, h = blockIdx.y, b = blockIdx.z;
    const size_t bh = (size_t)b * HN + h;

    float* CV = reinterpret_cast<float*>(smem + OFF_CV);
    uint16_t* CI = reinterpret_cast<uint16_t*>(smem + OFF_CI);
    int* CNT = reinterpret_cast<int*>(smem + OFF_CNT);
    float* CSUM = reinterpret_cast<float*>(smem + OFF_CSUM);
    uint32_t* THRU = reinterpret_cast<uint32_t*>(smem + OFF_THR);

    if (tid < MQ) THRU[tid] = 0u;   // enc(-inf)

    // ---- stage Q hi/lo (64 rows x 8 x16B slots = 512 slots, 2 per thread) ----
    {
        const uint4* qh = reinterpret_cast<const uint4*>(g_qhi + ((bh * LN + l0) << 6));
        const uint4* ql = reinterpret_cast<const uint4*>(g_qlo + ((bh * LN + l0) << 6));
        #pragma unroll
        for (int p = 0; p < 2; ++p) {
            const int slot = tid + NTHREADS * p;
            const int dst = (slot >> 3) * 144 + (slot & 7) * 16;
            *reinterpret_cast<uint4*>(smem + OFF_QHI + dst) = qh[slot];
            *reinterpret_cast<uint4*>(smem + OFF_QLO + dst) = ql[slot];
        }
    }

    // ---- stage K chunk 0 (512 slots per hi/lo, 2 per thread) ----
    const uint4* gkh = reinterpret_cast<const uint4*>(g_khi + ((bh * SN) << 6));
    const uint4* gkl = reinterpret_cast<const uint4*>(g_klo + ((bh * SN) << 6));
    {
        #pragma unroll
        for (int p = 0; p < 2; ++p) {
            const int slot = tid + NTHREADS * p;
            const int dst = (slot >> 3) * 144 + (slot & 7) * 16;
            *reinterpret_cast<uint4*>(smem + OFF_KB + dst) = gkh[slot];
            *reinterpret_cast<uint4*>(smem + OFF_KB + KTILE + dst) = gkl[slot];
        }
    }
    __syncthreads();

    // ---- ldmatrix lane addressing ----
    const int lrow  = lane & 15;
    const int lhalf = (lane >> 4) * 16;

    uint32_t ah[2][4][4];          // cached A-hi fragments
    uint32_t qloA[2];
    #pragma unroll
    for (int mt = 0; mt < 2; ++mt) {
        const uint32_t rowoff = (uint32_t)(32 * wq + 16 * mt + lrow) * 144 + lhalf;
        qloA[mt] = sb + OFF_QLO + rowoff;
        #pragma unroll
        for (int ks = 0; ks < 4; ++ks)
            ldsm_x4(ah[mt][ks], sb + OFF_QHI + rowoff + 32 * ks);
    }

    const uint32_t kbRow = (uint32_t)(16 * wk + lrow) * 144 + lhalf;
    const int gp = lane >> 2, tt = lane & 3;
    const unsigned qmask = 0xFu << (gp * 4);

    // per-(mt,rh) state: row = 32wq+16mt+8rh+gp, quarter = wk (replicated in quad)
    float runm[4], thrv[4], csum[4];
    int cnt[4];
    #pragma unroll
    for (int i = 0; i < 4; ++i) { runm[i] = -1e30f; thrv[i] = -1e30f; csum[i] = 0.f; cnt[i] = 0; }

    for (int c = 0; c < NCH; ++c) {
        const uint32_t kbh = sb + OFF_KB + (c & 1) * KBUF + kbRow;
        const uint32_t kbl = kbh + KTILE;

        float acc[2][2][4];
        #pragma unroll
        for (int mt = 0; mt < 2; ++mt)
            #pragma unroll
            for (int nt = 0; nt < 2; ++nt)
                #pragma unroll
                for (int i = 0; i < 4; ++i) acc[mt][nt][i] = 0.f;

        #pragma unroll
        for (int ks = 0; ks < 4; ++ks) {
            uint32_t bhf[4], blf[4], al0[4], al1[4];
            ldsm_x4(bhf, kbh + 32 * ks);
            ldsm_x4(blf, kbl + 32 * ks);
            ldsm_x4(al0, qloA[0] + 32 * ks);
            ldsm_x4(al1, qloA[1] + 32 * ks);

            mma_bf16(acc[0][0], ah[0][ks], bhf[0], bhf[2]);
            mma_bf16(acc[0][1], ah[0][ks], bhf[1], bhf[3]);
            mma_bf16(acc[1][0], ah[1][ks], bhf[0], bhf[2]);
            mma_bf16(acc[1][1], ah[1][ks], bhf[1], bhf[3]);

            mma_bf16(acc[0][0], ah[0][ks], blf[0], blf[2]);
            mma_bf16(acc[0][1], ah[0][ks], blf[1], blf[3]);
            mma_bf16(acc[1][0], ah[1][ks], blf[0], blf[2]);
            mma_bf16(acc[1][1], ah[1][ks], blf[1], blf[3]);

            mma_bf16(acc[0][0], al0, bhf[0], bhf[2]);
            mma_bf16(acc[0][1], al0, bhf[1], bhf[3]);
            mma_bf16(acc[1][0], al1, bhf[0], bhf[2]);
            mma_bf16(acc[1][1], al1, bhf[1], bhf[3]);
        }

        // prefetch next K chunk into registers
        uint4 pfh0, pfh1, pfl0, pfl1;
        if (c + 1 < NCH) {
            const int s0 = ((c + 1) * NK + (tid >> 3)) * 8 + (tid & 7);
            const int s1 = s0 + 32 * 8;
            pfh0 = gkh[s0]; pfh1 = gkh[s1];
            pfl0 = gkl[s0]; pfl1 = gkl[s1];
        }

        // ---- register-resident scan (no barrier, no z tile) ----
        #pragma unroll
        for (int mt = 0; mt < 2; ++mt) {
            #pragma unroll
            for (int rh = 0; rh < 2; ++rh) {
                const int idx = mt * 2 + rh;
                const int row = 32 * wq + 16 * mt + 8 * rh + gp;
                float v[4];
                v[0] = acc[mt][0][2 * rh];     v[1] = acc[mt][0][2 * rh + 1];
                v[2] = acc[mt][1][2 * rh];     v[3] = acc[mt][1][2 * rh + 1];

                float m4 = fmaxf(fmaxf(v[0], v[1]), fmaxf(v[2], v[3]));
                m4 = fmaxf(m4, __shfl_xor_sync(0xffffffffu, m4, 1));
                m4 = fmaxf(m4, __shfl_xor_sync(0xffffffffu, m4, 2));
                runm[idx] = fmaxf(runm[idx], m4);

                float thr = fmaxf(thrv[idx], runm[idx] - 1.0f);
                thr = fmaxf(thr, fdec(THRU[row]));          // cross-quarter share

                float* cv = CV + (row * 4 + wk) * CAPQ;
                uint16_t* ci = CI + (row * 4 + wk) * CAPQ;

                // guard: compaction (quad-divergent safe; lane tt==0 serial)
                if (cnt[idx] + 16 > CAPQ) {
                    if (tt == 0) {
                        int m = 0; float s = 0.f;
                        for (int q = 0; q < cnt[idx]; ++q) {
                            const float cq = cv[q];
                            if (cq > thr) { cv[m] = cq; ci[m] = ci[q]; s += cq; ++m; }
                        }
                        cnt[idx] = m; csum[idx] = s;
                    }
                    cnt[idx]  = __shfl_sync(qmask, cnt[idx],  gp * 4);
                    csum[idx] = __shfl_sync(qmask, csum[idx], gp * 4);
                }

                if (cnt[idx] + 16 <= CAPQ) {
                    // fast path: ballot-prefix parallel insert
                    int base = cnt[idx];
                    float sadd = 0.f;
                    #pragma unroll
                    for (int i = 0; i < 4; ++i) {
                        const bool p = v[i] > thr;
                        const unsigned full = __ballot_sync(0xffffffffu, p);
                        const unsigned mym = (full >> (gp * 4)) & 0xFu;
                        const int pos = base + __popc(mym & ((1u << tt) - 1u));
                        if (p) {
                            cv[pos] = v[i];
                            ci[pos] = (uint16_t)(c * NK + 16 * wk + 8 * (i >> 1) + 2 * tt + (i & 1));
                            sadd += v[i];
                        }
                        base += __popc(mym);
                    }
                    sadd += __shfl_xor_sync(0xffffffffu, sadd, 1);
                    sadd += __shfl_xor_sync(0xffffffffu, sadd, 2);
                    cnt[idx] = base; csum[idx] += sadd;
                } else {
                    // slow path: quad-serial insert with min-evict (rare)
                    for (int t = 0; t < 4; ++t) {
                        if (tt == t) {
                            #pragma unroll
                            for (int i = 0; i < 4; ++i) {
                                if (v[i] > thr) {
                                    const uint16_t key =
                                        (uint16_t)(c * NK + 16 * wk + 8 * (i >> 1) + 2 * tt + (i & 1));
                                    if (cnt[idx] < CAPQ) {
                                        cv[cnt[idx]] = v[i]; ci[cnt[idx]] = key;
                                        csum[idx] += v[i]; ++cnt[idx];
                                    } else {
                                        int am = 0; float mn = cv[0];
                                        for (int q = 1; q < CAPQ; ++q)
                                            if (cv[q] < mn) { mn = cv[q]; am = q; }
                                        if (v[i] > mn) {
                                            csum[idx] += v[i] - mn;
                                            cv[am] = v[i]; ci[am] = key;
                                        }
                                    }
                                }
                            }
                        }
                        cnt[idx]  = __shfl_sync(qmask, cnt[idx],  gp * 4 + t);
                        csum[idx] = __shfl_sync(qmask, csum[idx], gp * 4 + t);
                    }
                }

                // streaming tau lower bound from this quarter's list
                if (cnt[idx] > 0)
                    thr = fmaxf(thr, (csum[idx] - 1.0f) / (float)cnt[idx]);
                thrv[idx] = thr;
                if (tt == 0) atomicMax(&THRU[row], fenc(thr));
            }
        }

        // ---- stage prefetched chunk into the other buffer ----
        if (c + 1 < NCH) {
            char* kb = smem + OFF_KB + ((c + 1) & 1) * KBUF;
            const int d0 = (tid >> 3) * 144 + (tid & 7) * 16;
            const int d1 = d0 + 32 * 144;
            *reinterpret_cast<uint4*>(kb + d0) = pfh0;
            *reinterpret_cast<uint4*>(kb + d1) = pfh1;
            *reinterpret_cast<uint4*>(kb + KTILE + d0) = pfl0;
            *reinterpret_cast<uint4*>(kb + KTILE + d1) = pfl1;
        }
        __syncthreads();
    }

    // publish per-(row,quarter) cnt/csum
    if (tt == 0) {
        #pragma unroll
        for (int mt = 0; mt < 2; ++mt)
            #pragma unroll
            for (int rh = 0; rh < 2; ++rh) {
                const int idx = mt * 2 + rh;
                const int row = 32 * wq + 16 * mt + 8 * rh + gp;
                CNT[row * 4 + wk] = cnt[idx];
                CSUM[row * 4 + wk] = csum[idx];
            }
    }
    __syncthreads();

    // ---- quad-cooperative Michelot tau (exact on candidate superset) ----
    {
        const int frow = warp * 8 + (lane >> 2), ft4 = lane & 3;
        float* cv = CV + (frow * 4 + ft4) * CAPQ;
        uint16_t* ci = CI + (frow * 4 + ft4) * CAPQ;
        int n = CNT[frow * 4 + ft4];
        float s = CSUM[frow * 4 + ft4];

        s += __shfl_xor_sync(0xffffffffu, s, 1);
        s += __shfl_xor_sync(0xffffffffu, s, 2);
        int ctot = n;
        ctot += __shfl_xor_sync(0xffffffffu, ctot, 1);
        ctot += __shfl_xor_sync(0xffffffffu, ctot, 2);
        float tau = (s - 1.0f) / (float)ctot;

        bool changed = true;
        while (__any_sync(0xffffffffu, changed)) {
            float s2 = 0.f; int c2 = 0;
            for (int i = 0; i < n; ++i) {
                const float vv = cv[i];
                if (vv > tau) { s2 += vv; ++c2; }
            }
            s2 += __shfl_xor_sync(0xffffffffu, s2, 1);
            s2 += __shfl_xor_sync(0xffffffffu, s2, 2);
            c2 += __shfl_xor_sync(0xffffffffu, c2, 1);
            c2 += __shfl_xor_sync(0xffffffffu, c2, 2);
            const float tn = (s2 - 1.0f) / (float)c2;
            changed = (tn > tau);
            if (changed) tau = tn;
        }

        int m = 0;
        for (int i = 0; i < n; ++i) {
            const float vv = cv[i];
            if (vv > tau) { cv[m] = vv - tau; ci[m] = ci[i]; ++m; }
        }
        CNT[frow * 4 + ft4] = m;
    }
    __syncthreads();

    // ---- sparse AV: warp w -> rows 8w..8w+7; lane covers d=lane, lane+32 ----
    {
        const float* vb = V + ((size_t)b * SN * HN + h) * DN;
        for (int rr = 0; rr < 8; ++rr) {
            const int row = warp * 8 + rr;
            float o0 = 0.f, o1 = 0.f;
            #pragma unroll
            for (int t = 0; t < 4; ++t) {
                const int m = CNT[row * 4 + t];
                const float* cvr = CV + (row * 4 + t) * CAPQ;
                const uint16_t* cir = CI + (row * 4 + t) * CAPQ;
                for (int i = 0; i < m; ++i) {
                    const float p = cvr[i];
                    const int j = cir[i];
                    const float* vr = vb + (size_t)j * HN * DN;
                    o0 += p * vr[lane];
                    o1 += p * vr[lane + 32];
                }
            }
            float* orow = O + (((size_t)b * LN + l0 + row) * HN + h) * DN;
            orow[lane]      = o0;
            orow[lane + 32] = o1;
        }
    }
}

// ---------------- launch ----------------
extern "C" void kernel_launch(void* const* d_in, const int* in_sizes, int n_in,
                              void* d_out, int out_size) {
    const float* Q = (const float*)d_in[0];
    const float* K = (const float*)d_in[1];
    const float* V = (const float*)d_in[2];
    float* O = (float*)d_out;

    prep_kernel<<<4096, 256>>>(Q, K);

    cudaFuncSetAttribute(sparsemax_attn_mma,
                         cudaFuncAttributeMaxDynamicSharedMemorySize, SMEM_BYTES);
    dim3 grid(LN / MQ, HN, BN);
    sparsemax_attn_mma<<<grid, NTHREADS, SMEM_BYTES>>>(V, O);
}

// round 12
// speedup vs baseline: 1.2061x; 1.2061x over previous
#include <cuda_runtime.h>
#include <cuda_bf16.h>
#include <cstdint>

// ---------------- problem shape (fixed) ----------------
constexpr int BN = 8, LN = 1024, SN = 1024, HN = 16, EN = 64, DN = 64;

constexpr int MQ  = 64;            // queries per CTA
constexpr int NK  = 64;            // keys per chunk
constexpr int NCH = SN / NK;       // 16
constexpr int NTHREADS = 256;      // 8 warps
constexpr int CAPQ = 24;           // candidate capacity per (row, quarter)

constexpr int Z_STRIDE  = 76;      // f32 per z row

// ---------------- smem layout (bytes) ----------------
constexpr int QTILE   = MQ * 144;                  // 9216 (hi or lo)
constexpr int OFF_QHI = 0;
constexpr int OFF_QLO = QTILE;                     // 9216
constexpr int OFF_KB  = 2 * QTILE;                 // 18432 ; 2 buffers
constexpr int KTILE   = NK * 144;                  // 9216
constexpr int KBUF    = 2 * KTILE;                 // hi+lo = 18432
constexpr int OFF_Z   = OFF_KB + 2 * KBUF;         // 55296
constexpr int OFF_CV  = OFF_Z + MQ * Z_STRIDE * 4; // 74752 ; float[64*4*CAPQ]
constexpr int OFF_CI  = OFF_CV + MQ * 4 * CAPQ * 4;// 99328 ; u16
constexpr int OFF_CNT = OFF_CI + MQ * 4 * CAPQ * 2;// 111616 ; int[256]
constexpr int SMEM_BYTES = OFF_CNT + MQ * 4 * 4;   // 112640 (110 KB -> 2 CTAs/SM)

// ---------------- prepped bf16 hi/lo tensors ([b][h][l|s][e]) ----------------
__device__ __nv_bfloat16 g_qhi[(size_t)BN*HN*LN*EN];
__device__ __nv_bfloat16 g_qlo[(size_t)BN*HN*LN*EN];
__device__ __nv_bfloat16 g_khi[(size_t)BN*HN*SN*EN];
__device__ __nv_bfloat16 g_klo[(size_t)BN*HN*SN*EN];

// ---------------- PTX helpers ----------------
__device__ __forceinline__ uint32_t smem_to_u32(const void* p) {
    uint32_t a;
    asm("{ .reg .u64 t; cvta.to.shared.u64 t, %1; cvt.u32.u64 %0, t; }" : "=r"(a) : "l"(p));
    return a;
}
__device__ __forceinline__ void ldsm_x4(uint32_t r[4], uint32_t addr) {
    asm volatile("ldmatrix.sync.aligned.m8n8.x4.shared.b16 {%0,%1,%2,%3}, [%4];"
                 : "=r"(r[0]), "=r"(r[1]), "=r"(r[2]), "=r"(r[3]) : "r"(addr));
}
__device__ __forceinline__ void mma_bf16(float d[4], const uint32_t a[4],
                                         uint32_t b0, uint32_t b1) {
    asm volatile("mma.sync.aligned.m16n8k16.row.col.f32.bf16.bf16.f32 "
                 "{%0,%1,%2,%3}, {%4,%5,%6,%7}, {%8,%9}, {%0,%1,%2,%3};"
                 : "+f"(d[0]), "+f"(d[1]), "+f"(d[2]), "+f"(d[3])
                 : "r"(a[0]), "r"(a[1]), "r"(a[2]), "r"(a[3]), "r"(b0), "r"(b1));
}

// ---------------- prep: fp32 -> bf16 hi/lo, [b,l,h,e] -> [b,h,l,e] ----------------
__global__ void prep_kernel(const float* __restrict__ Q, const float* __restrict__ K) {
    const size_t total = (size_t)BN * LN * HN * EN;
    for (size_t i = (size_t)blockIdx.x * blockDim.x + threadIdx.x; i < total;
         i += (size_t)gridDim.x * blockDim.x) {
        const int e = (int)(i & 63);
        const int h = (int)((i >> 6) & 15);
        const int l = (int)((i >> 10) & 1023);
        const int b = (int)(i >> 20);
        const size_t o = ((((size_t)b * HN + h) * LN + l) << 6) + e;

        float q = Q[i] * 0.125f;                        // fold 1/sqrt(E)
        __nv_bfloat16 qh = __float2bfloat16(q);
        g_qhi[o] = qh;
        g_qlo[o] = __float2bfloat16(q - __bfloat162float(qh));

        float k = K[i];
        __nv_bfloat16 kh = __float2bfloat16(k);
        g_khi[o] = kh;
        g_klo[o] = __float2bfloat16(k - __bfloat162float(kh));
    }
}

// ---------------- main kernel ----------------
__global__ __launch_bounds__(NTHREADS, 2)
void sparsemax_attn_mma(const float* __restrict__ V, float* __restrict__ O) {
    extern __shared__ char smem[];
    const uint32_t sb = smem_to_u32(smem);
    const int tid = threadIdx.x, lane = tid & 31, warp = tid >> 5;
    const int wq = warp & 1, wk = warp >> 1;        // 2 q-groups x 4 k-groups
    const int l0 = blockIdx.x * MQ, h = blockIdx.y, b = blockIdx.z;
    const size_t bh = (size_t)b * HN + h;

    // ---- stage Q hi/lo into padded smem tiles (512 slots, 2 per thread) ----
    {
        const uint4* qh = reinterpret_cast<const uint4*>(g_qhi + ((bh * LN + l0) << 6));
        const uint4* ql = reinterpret_cast<const uint4*>(g_qlo + ((bh * LN + l0) << 6));
        #pragma unroll
        for (int p = 0; p < 2; ++p) {
            const int slot = tid + NTHREADS * p;
            const int dst = (slot >> 3) * 144 + (slot & 7) * 16;
            *reinterpret_cast<uint4*>(smem + OFF_QHI + dst) = qh[slot];
            *reinterpret_cast<uint4*>(smem + OFF_QLO + dst) = ql[slot];
        }
    }

    // ---- stage K chunk 0 (512 slots per hi/lo, 2 per thread) ----
    const uint4* gkh = reinterpret_cast<const uint4*>(g_khi + ((bh * SN) << 6));
    const uint4* gkl = reinterpret_cast<const uint4*>(g_klo + ((bh * SN) << 6));
    const int d0 = (tid >> 3) * 144 + (tid & 7) * 16;   // row tid>>3 (0..31)
    const int d1 = d0 + 32 * 144;                        // row +32
    {
        *reinterpret_cast<uint4*>(smem + OFF_KB + d0) = gkh[tid];
        *reinterpret_cast<uint4*>(smem + OFF_KB + d1) = gkh[tid + 256];
        *reinterpret_cast<uint4*>(smem + OFF_KB + KTILE + d0) = gkl[tid];
        *reinterpret_cast<uint4*>(smem + OFF_KB + KTILE + d1) = gkl[tid + 256];
    }
    __syncthreads();

    // ---- ldmatrix lane addressing ----
    const int lrow  = lane & 15;
    const int lhalf = (lane >> 4) * 16;

    // cache A-hi fragments for the whole CTA lifetime: [mt][ks][4]
    uint32_t ah[2][4][4];
    uint32_t qloA[2];  // per-mt base addrs for A-lo reloads
    #pragma unroll
    for (int mt = 0; mt < 2; ++mt) {
        const uint32_t rowoff = (uint32_t)(32 * wq + 16 * mt + lrow) * 144 + lhalf;
        qloA[mt] = sb + OFF_QLO + rowoff;
        #pragma unroll
        for (int ks = 0; ks < 4; ++ks)
            ldsm_x4(ah[mt][ks], sb + OFF_QHI + rowoff + 32 * ks);
    }

    // per-lane candidate state: row = warp*8 + (lane>>2), quarter = lane&3
    const int rsub = lane >> 2, t4 = lane & 3;
    const int myrow = warp * 8 + rsub;
    float runmax = -1e30f;
    float thr    = -1e30f;   // max(runmax-1, streaming tau lower bound)
    float csum   = 0.f;      // sum of current candidates (this lane's list)
    int cnt = 0;
    float* cv = reinterpret_cast<float*>(smem + OFF_CV) + (myrow * 4 + t4) * CAPQ;
    uint16_t* cix = reinterpret_cast<uint16_t*>(smem + OFF_CI) + (myrow * 4 + t4) * CAPQ;

    const uint32_t kbRow = (uint32_t)(16 * wk + lrow) * 144 + lhalf;
    const int g = lane >> 2, tt = lane & 3;

    for (int c = 0; c < NCH; ++c) {
        const int buf = c & 1;
        const uint32_t kbh = sb + OFF_KB + buf * KBUF + kbRow;
        const uint32_t kbl = kbh + KTILE;

        float acc[2][2][4];
        #pragma unroll
        for (int mt = 0; mt < 2; ++mt)
            #pragma unroll
            for (int nt = 0; nt < 2; ++nt)
                #pragma unroll
                for (int i = 0; i < 4; ++i) acc[mt][nt][i] = 0.f;

        #pragma unroll
        for (int ks = 0; ks < 4; ++ks) {
            uint32_t bhf[4], blf[4], al0[4], al1[4];
            ldsm_x4(bhf, kbh + 32 * ks);
            ldsm_x4(blf, kbl + 32 * ks);
            ldsm_x4(al0, qloA[0] + 32 * ks);
            ldsm_x4(al1, qloA[1] + 32 * ks);

            mma_bf16(acc[0][0], ah[0][ks], bhf[0], bhf[2]);
            mma_bf16(acc[0][1], ah[0][ks], bhf[1], bhf[3]);
            mma_bf16(acc[1][0], ah[1][ks], bhf[0], bhf[2]);
            mma_bf16(acc[1][1], ah[1][ks], bhf[1], bhf[3]);

            mma_bf16(acc[0][0], ah[0][ks], blf[0], blf[2]);
            mma_bf16(acc[0][1], ah[0][ks], blf[1], blf[3]);
            mma_bf16(acc[1][0], ah[1][ks], blf[0], blf[2]);
            mma_bf16(acc[1][1], ah[1][ks], blf[1], blf[3]);

            mma_bf16(acc[0][0], al0, bhf[0], bhf[2]);
            mma_bf16(acc[0][1], al0, bhf[1], bhf[3]);
            mma_bf16(acc[1][0], al1, bhf[0], bhf[2]);
            mma_bf16(acc[1][1], al1, bhf[1], bhf[3]);
        }

        // prefetch next K chunk into registers (hide L2 latency)
        uint4 pfh0, pfh1, pfl0, pfl1;
        if (c + 1 < NCH) {
            const int s0 = (c + 1) * NK * 8 + tid;
            const int s1 = s0 + 256;
            pfh0 = gkh[s0]; pfh1 = gkh[s1];
            pfl0 = gkl[s0]; pfl1 = gkl[s1];
        }

        // ---- write scores to z ----
        #pragma unroll
        for (int mt = 0; mt < 2; ++mt)
            #pragma unroll
            for (int nt = 0; nt < 2; ++nt) {
                const int row0 = 32 * wq + 16 * mt + g;
                const int col  = 16 * wk + 8 * nt + 2 * tt;
                float2 lo2; lo2.x = acc[mt][nt][0]; lo2.y = acc[mt][nt][1];
                float2 hi2; hi2.x = acc[mt][nt][2]; hi2.y = acc[mt][nt][3];
                *reinterpret_cast<float2*>(smem + OFF_Z + ((size_t)row0 * Z_STRIDE + col) * 4) = lo2;
                *reinterpret_cast<float2*>(smem + OFF_Z + ((size_t)(row0 + 8) * Z_STRIDE + col) * 4) = hi2;
            }
        __syncthreads();

        // ---- scan: lane owns (myrow, cols 16*t4 .. 16*t4+15) ----
        {
            const float* zr = reinterpret_cast<const float*>(smem + OFF_Z)
                              + (size_t)myrow * Z_STRIDE + 16 * t4;
            float v[16];
            #pragma unroll
            for (int i = 0; i < 4; ++i) {
                const float4 f = reinterpret_cast<const float4*>(zr)[i];
                v[4*i+0] = f.x; v[4*i+1] = f.y; v[4*i+2] = f.z; v[4*i+3] = f.w;
            }
            float bmax = v[0];
            #pragma unroll
            for (int i = 1; i < 16; ++i) bmax = fmaxf(bmax, v[i]);
            bmax = fmaxf(bmax, __shfl_xor_sync(0xffffffffu, bmax, 1));
            bmax = fmaxf(bmax, __shfl_xor_sync(0xffffffffu, bmax, 2));
            runmax = fmaxf(runmax, bmax);
            thr = fmaxf(thr, runmax - 1.0f);

            #pragma unroll
            for (int i = 0; i < 16; ++i) {
                if (v[i] > thr) {
                    if (cnt == CAPQ) {       // recompact with freshest thr
                        int m = 0; float s = 0.f;
                        for (int q = 0; q < CAPQ; ++q) {
                            const float cq = cv[q];
                            if (cq > thr) { cv[m] = cq; cix[m] = cix[q]; s += cq; ++m; }
                        }
                        cnt = m; csum = s;
                    }
                    if (cnt < CAPQ) {
                        cv[cnt] = v[i];
                        cix[cnt] = (uint16_t)(c * NK + 16 * t4 + i);
                        csum += v[i];
                        ++cnt;
                    } else {
                        // evict min if new value larger (practically unreachable)
                        int am = 0; float mn = cv[0];
                        for (int q = 1; q < CAPQ; ++q)
                            if (cv[q] < mn) { mn = cv[q]; am = q; }
                        if (v[i] > mn) {
                            csum += v[i] - mn;
                            cv[am] = v[i];
                            cix[am] = (uint16_t)(c * NK + 16 * t4 + i);
                        }
                    }
                }
            }

            // streaming tau lower bound (valid for any subset C of a row:
            // (sum_C - 1)/|C| <= tau*), quad-reduced across the row's 4 lists
            float sq = csum; int cq = cnt;
            sq += __shfl_xor_sync(0xffffffffu, sq, 1);
            sq += __shfl_xor_sync(0xffffffffu, sq, 2);
            cq += __shfl_xor_sync(0xffffffffu, cq, 1);
            cq += __shfl_xor_sync(0xffffffffu, cq, 2);
            if (cq > 0) thr = fmaxf(thr, (sq - 1.0f) / (float)cq);
        }

        // ---- stage prefetched chunk into the other buffer ----
        if (c + 1 < NCH) {
            char* kb = smem + OFF_KB + ((c + 1) & 1) * KBUF;
            *reinterpret_cast<uint4*>(kb + d0) = pfh0;
            *reinterpret_cast<uint4*>(kb + d1) = pfh1;
            *reinterpret_cast<uint4*>(kb + KTILE + d0) = pfl0;
            *reinterpret_cast<uint4*>(kb + KTILE + d1) = pfl1;
        }
        __syncthreads();
    }

    // ---- quad-cooperative Michelot tau (exact on candidate superset) ----
    {
        float s = csum;
        s += __shfl_xor_sync(0xffffffffu, s, 1);
        s += __shfl_xor_sync(0xffffffffu, s, 2);
        int ctot = cnt;
        ctot += __shfl_xor_sync(0xffffffffu, ctot, 1);
        ctot += __shfl_xor_sync(0xffffffffu, ctot, 2);
        float tau = (s - 1.0f) / (float)ctot;

        bool changed = true;
        while (__any_sync(0xffffffffu, changed)) {
            float s2 = 0.f; int c2 = 0;
            for (int i = 0; i < cnt; ++i) {
                const float vv = cv[i];
                if (vv > tau) { s2 += vv; ++c2; }
            }
            s2 += __shfl_xor_sync(0xffffffffu, s2, 1);
            s2 += __shfl_xor_sync(0xffffffffu, s2, 2);
            c2 += __shfl_xor_sync(0xffffffffu, c2, 1);
            c2 += __shfl_xor_sync(0xffffffffu, c2, 2);
            const float tn = (s2 - 1.0f) / (float)c2;
            changed = (tn > tau);
            if (changed) tau = tn;
        }

        // compact to p = v - tau > 0
        int m = 0;
        for (int i = 0; i < cnt; ++i) {
            const float vv = cv[i];
            if (vv > tau) { cv[m] = vv - tau; cix[m] = cix[i]; ++m; }
        }
        reinterpret_cast<int*>(smem + OFF_CNT)[myrow * 4 + t4] = m;
    }
    __syncthreads();

    // ---- sparse AV: warp w -> rows 8w..8w+7; lane covers d=lane, lane+32 ----
    {
        const float* vb = V + ((size_t)b * SN * HN + h) * DN;
        const int* scnt = reinterpret_cast<const int*>(smem + OFF_CNT);
        for (int rr = 0; rr < 8; ++rr) {
            const int row = warp * 8 + rr;
            float o0 = 0.f, o1 = 0.f;
            #pragma unroll
            for (int t = 0; t < 4; ++t) {
                const int m = scnt[row * 4 + t];
                const float* cvr = reinterpret_cast<const float*>(smem + OFF_CV)
                                   + (row * 4 + t) * CAPQ;
                const uint16_t* cir = reinterpret_cast<const uint16_t*>(smem + OFF_CI)
                                   + (row * 4 + t) * CAPQ;
                for (int i = 0; i < m; ++i) {
                    const float p = cvr[i];
                    const int j = cir[i];
                    const float* vr = vb + (size_t)j * HN * DN;
                    o0 += p * vr[lane];
                    o1 += p * vr[lane + 32];
                }
            }
            float* orow = O + (((size_t)b * LN + l0 + row) * HN + h) * DN;
            orow[lane]      = o0;
            orow[lane + 32] = o1;
        }
    }
}

// ---------------- launch ----------------
extern "C" void kernel_launch(void* const* d_in, const int* in_sizes, int n_in,
                              void* d_out, int out_size) {
    const float* Q = (const float*)d_in[0];
    const float* K = (const float*)d_in[1];
    const float* V = (const float*)d_in[2];
    float* O = (float*)d_out;

    prep_kernel<<<4096, 256>>>(Q, K);

    cudaFuncSetAttribute(sparsemax_attn_mma,
                         cudaFuncAttributeMaxDynamicSharedMemorySize, SMEM_BYTES);
    dim3 grid(LN / MQ, HN, BN);
    sparsemax_attn_mma<<<grid, NTHREADS, SMEM_BYTES>>>(V, O);
}